// round 12
// baseline (speedup 1.0000x reference)
#include <cuda_runtime.h>
#include <cuda_bf16.h>
#include <math.h>
#include <stdint.h>

#define NL 12
#define DMODEL 1152
#define NHD 4
#define HDIM 256
#define FDIM 6912
#define VOC 32768
#define TT 128
#define CCTX 1920
#define SS 2048
#define QKVW 1536
#define CAPV 50.0f
#define SCL 0.0625f

__device__ __align__(256) float g_h[TT * DMODEL];
__device__ __align__(256) float g_x[TT * DMODEL];
__device__ __align__(256) float g_qkv[TT * QKVW];
__device__ __align__(256) float g_q[NHD * TT * HDIM];
__device__ __align__(256) uint32_t g_khi[SS * HDIM / 2];
__device__ __align__(256) uint32_t g_klo[SS * HDIM / 2];
__device__ __align__(256) uint32_t g_vhi[HDIM * SS / 2];
__device__ __align__(256) uint32_t g_vlo[HDIM * SS / 2];
__device__ __align__(256) float g_scores[NHD * TT * SS];
__device__ __align__(256) float g_attno[TT * NHD * HDIM];
__device__ __align__(256) float g_proj[TT * DMODEL];
__device__ __align__(256) float g_ffa[TT * FDIM];
__device__ __align__(256) float g_ffb[TT * FDIM];
__device__ __align__(256) float g_part[8 * 1024 * 1024];

// ---------- helpers ----------
__device__ __forceinline__ uint32_t smem_u32(const void* p) {
    uint32_t a;
    asm("{ .reg .u64 t; cvta.to.shared.u64 t, %1; cvt.u32.u64 %0, t; }" : "=r"(a) : "l"(p));
    return a;
}
__device__ __forceinline__ uint32_t sw128(uint32_t o) { return o ^ ((o >> 3) & 0x70u); }
__device__ __forceinline__ uint32_t packbf2(float a, float b) {
    __nv_bfloat162 t = __floats2bfloat162_rn(a, b);
    return *(uint32_t*)&t;
}
__device__ __forceinline__ void hilo(float v, float& h, float& l) {
    __nv_bfloat16 hb = __float2bfloat16_rn(v);
    h = __bfloat162float(hb);
    l = v - h;
}
__device__ __forceinline__ void ldm4(uint32_t* r, uint32_t a) {
    asm volatile("ldmatrix.sync.aligned.m8n8.x4.shared.b16 {%0,%1,%2,%3}, [%4];"
                 : "=r"(r[0]), "=r"(r[1]), "=r"(r[2]), "=r"(r[3]) : "r"(a));
}
__device__ __forceinline__ void mma16816(float* c, const uint32_t* a, uint32_t b0, uint32_t b1) {
    asm volatile(
        "mma.sync.aligned.m16n8k16.row.col.f32.bf16.bf16.f32 "
        "{%0,%1,%2,%3}, {%4,%5,%6,%7}, {%8,%9}, {%0,%1,%2,%3};"
        : "+f"(c[0]), "+f"(c[1]), "+f"(c[2]), "+f"(c[3])
        : "r"(a[0]), "r"(a[1]), "r"(a[2]), "r"(a[3]), "r"(b0), "r"(b1));
}
__device__ __forceinline__ void st8(uint32_t a, uint32_t v0, uint32_t v1) {
    asm volatile("st.shared.v2.b32 [%0], {%1,%2};" :: "r"(a), "r"(v0), "r"(v1) : "memory");
}
__device__ __forceinline__ void st16(uint32_t a, uint4 v) {
    asm volatile("st.shared.v4.b32 [%0], {%1,%2,%3,%4};"
                 :: "r"(a), "r"(v.x), "r"(v.y), "r"(v.z), "r"(v.w) : "memory");
}
__device__ __forceinline__ void store4(uint32_t base, uint32_t ob, float4 v) {
    float h0, l0, h1, l1, h2, l2, h3, l3;
    hilo(v.x, h0, l0); hilo(v.y, h1, l1); hilo(v.z, h2, l2); hilo(v.w, h3, l3);
    st8(base + sw128(ob),      packbf2(h0, h1), packbf2(h2, h3));
    st8(base + sw128(ob + 64), packbf2(l0, l1), packbf2(l2, l3));
}

// ============================================================
// bf16x3 mma GEMM. Single 32KB smem buffer, 2 CTAs/SM.
// BMODE 1: B fp32 [K,N] (N contig, transpose+convert on load)
// BMODE 2: B pre-packed bf16 pairs: Bhi/Blo u32 [N][K/2]
// ============================================================
#define SMEM_GEMM_BYTES 32768

template <int BMODE>
__global__ void __launch_bounds__(256, 2) mmagemm(
    const float* __restrict__ Aall, int lda, long sAb,
    const float* __restrict__ Bf,
    const uint32_t* __restrict__ Bhi, const uint32_t* __restrict__ Blo,
    int ldb, float* __restrict__ Call, int ldc, long sCb,
    float* __restrict__ Cpart, int N, int K, int splits)
{
    extern __shared__ char smraw[];
    const uint32_t sb = smem_u32(smraw);
    const uint32_t ab = sb, bb = sb + 16384;
    const int tid = threadIdx.x;
    const int lane = tid & 31, w = tid >> 5;
    const int wm = w & 1, wn = w >> 1;
    const int nb = blockIdx.x, split = blockIdx.y, batch = blockIdx.z;
    const int Kc = K / splits;
    const int NC = Kc >> 5;

    const float* A = Aall + (long)batch * sAb + (long)split * Kc;
    const float* BfT = Bf ? (Bf + (long)((long)split * Kc) * ldb + nb * 128) : nullptr;
    const int Kh = K >> 1;
    const long bpk = (long)(nb * 128) * Kh + (split * Kc >> 1);

    float c[4][4][4];
    #pragma unroll
    for (int a = 0; a < 4; a++)
        #pragma unroll
        for (int b = 0; b < 4; b++)
            #pragma unroll
            for (int r = 0; r < 4; r++) c[a][b][r] = 0.f;

    const int row = tid >> 1, half = tid & 1;
    const int bn = tid & 127, bkg = tid >> 7;

    const int m0 = wm * 64, n0 = wn * 32;
    const uint32_t lrow = lane & 15;
    const uint32_t lsel = (lane >> 4) * 16;

    for (int i = 0; i < NC; i++) {
        // ---- fill A (fp32 K-major, convert) ----
        {
            const float* ap = A + (long)row * lda + i * 32 + half * 16;
            const uint32_t o = row * 128 + half * 32;
            #pragma unroll
            for (int q = 0; q < 4; q++)
                store4(ab, o + q * 8, ((const float4*)ap)[q]);
        }
        // ---- fill B ----
        if (BMODE == 1) {
            const float* bp = BfT + ((long)i * 32 + bkg * 16) * ldb + bn;
            const uint32_t o = bn * 128 + bkg * 32;
            #pragma unroll
            for (int g = 0; g < 4; g++) {
                float4 v = make_float4(bp[(long)(g * 4 + 0) * ldb], bp[(long)(g * 4 + 1) * ldb],
                                       bp[(long)(g * 4 + 2) * ldb], bp[(long)(g * 4 + 3) * ldb]);
                store4(bb, o + g * 8, v);
            }
        } else {
            const long u = bpk + (long)row * Kh + i * 16 + half * 8;
            uint4 h0 = *(const uint4*)(Bhi + u);
            uint4 h1 = *(const uint4*)(Bhi + u + 4);
            uint4 l0 = *(const uint4*)(Blo + u);
            uint4 l1 = *(const uint4*)(Blo + u + 4);
            const uint32_t o = row * 128 + half * 32;
            st16(bb + sw128(o), h0);
            st16(bb + sw128(o + 16), h1);
            st16(bb + sw128(o + 64), l0);
            st16(bb + sw128(o + 80), l1);
        }
        __syncthreads();

        // ---- mma ----
        #pragma unroll
        for (int j = 0; j < 2; j++) {
            const uint32_t cb = j * 32;
            uint32_t ahi[4][4], alo[4][4], bhi[2][4], blo[2][4];
            #pragma unroll
            for (int mt = 0; mt < 4; mt++) {
                uint32_t o = (m0 + mt * 16 + lrow) * 128 + cb + lsel;
                ldm4(ahi[mt], ab + sw128(o));
                ldm4(alo[mt], ab + sw128(o + 64));
            }
            #pragma unroll
            for (int pp = 0; pp < 2; pp++) {
                uint32_t o = (n0 + pp * 16 + lrow) * 128 + cb + lsel;
                ldm4(bhi[pp], bb + sw128(o));
                ldm4(blo[pp], bb + sw128(o + 64));
            }
            #pragma unroll
            for (int mt = 0; mt < 4; mt++)
                #pragma unroll
                for (int nt = 0; nt < 4; nt++) {
                    int pp = nt >> 1, qq = nt & 1;
                    mma16816(c[mt][nt], ahi[mt], bhi[pp][qq], bhi[pp][qq + 2]);
                    mma16816(c[mt][nt], alo[mt], bhi[pp][qq], bhi[pp][qq + 2]);
                    mma16816(c[mt][nt], ahi[mt], blo[pp][qq], blo[pp][qq + 2]);
                }
        }
        __syncthreads();
    }

    // ---- epilogue ----
    float* Cb;
    long ldx;
    if (splits == 1) { Cb = Call + (long)batch * sCb + nb * 128; ldx = ldc; }
    else { Cb = Cpart + ((long)(batch * splits + split) * 128) * N + nb * 128; ldx = N; }
    #pragma unroll
    for (int mt = 0; mt < 4; mt++)
        #pragma unroll
        for (int nt = 0; nt < 4; nt++) {
            int r0 = m0 + mt * 16 + (lane >> 2);
            int c0 = n0 + nt * 8 + (lane & 3) * 2;
            *(float2*)&Cb[(long)r0 * ldx + c0] = make_float2(c[mt][nt][0], c[mt][nt][1]);
            *(float2*)&Cb[(long)(r0 + 8) * ldx + c0] = make_float2(c[mt][nt][2], c[mt][nt][3]);
        }
}

__global__ void reduce_kernel(const float* __restrict__ part, float* __restrict__ C,
                              int ldc, long sCb, int N, int splits, long total)
{
    long idx = (long)blockIdx.x * blockDim.x + threadIdx.x;
    if (idx >= total) return;
    int n = (int)(idx % N);
    long r = idx / N;
    int m = (int)(r % 128);
    int b = (int)(r / 128);
    float s = 0.f;
    for (int sp = 0; sp < splits; sp++)
        s += part[((long)(b * splits + sp) * 128 + m) * N + n];
    C[(long)b * sCb + (long)m * ldc + n] = s;
}

// ---------- reductions ----------
__device__ __forceinline__ float blockReduceSum(float v) {
    __shared__ float sh[33];
    __syncthreads();
    int lane = threadIdx.x & 31, wid = threadIdx.x >> 5;
    #pragma unroll
    for (int o = 16; o; o >>= 1) v += __shfl_xor_sync(0xffffffffu, v, o);
    if (lane == 0) sh[wid] = v;
    __syncthreads();
    int nw = (blockDim.x + 31) >> 5;
    v = (threadIdx.x < nw) ? sh[threadIdx.x] : 0.f;
    if (wid == 0) {
        #pragma unroll
        for (int o = 16; o; o >>= 1) v += __shfl_xor_sync(0xffffffffu, v, o);
        if (lane == 0) sh[32] = v;
    }
    __syncthreads();
    return sh[32];
}
__device__ __forceinline__ float blockReduceMax(float v) {
    __shared__ float sh[33];
    __syncthreads();
    int lane = threadIdx.x & 31, wid = threadIdx.x >> 5;
    #pragma unroll
    for (int o = 16; o; o >>= 1) v = fmaxf(v, __shfl_xor_sync(0xffffffffu, v, o));
    if (lane == 0) sh[wid] = v;
    __syncthreads();
    int nw = (blockDim.x + 31) >> 5;
    v = (threadIdx.x < nw) ? sh[threadIdx.x] : -3.4e38f;
    if (wid == 0) {
        #pragma unroll
        for (int o = 16; o; o >>= 1) v = fmaxf(v, __shfl_xor_sync(0xffffffffu, v, o));
        if (lane == 0) sh[32] = v;
    }
    __syncthreads();
    return sh[32];
}

// ---------- elementwise / pack producers ----------
__global__ void copy_kernel(const float* __restrict__ s, float* __restrict__ d, int n) {
    int i = blockIdx.x * blockDim.x + threadIdx.x;
    if (i < n) d[i] = s[i];
}
// kv_k slice [CCTX][HDIM] -> khi/klo pairs along HDIM
__global__ void packk_kernel(const float* __restrict__ src) {
    int i = blockIdx.x * blockDim.x + threadIdx.x;
    if (i >= CCTX * HDIM / 2) return;
    int r = i / (HDIM / 2), cc = i % (HDIM / 2);
    float x0 = src[r * HDIM + 2 * cc], x1 = src[r * HDIM + 2 * cc + 1];
    float h0, l0, h1, l1;
    hilo(x0, h0, l0); hilo(x1, h1, l1);
    g_khi[r * (HDIM / 2) + cc] = packbf2(h0, h1);
    g_klo[r * (HDIM / 2) + cc] = packbf2(l0, l1);
}
// kv_v slice [HDIM][CCTX] -> vhi/vlo pairs along S (first CCTX/2 cols)
__global__ void packv_kernel(const float* __restrict__ src) {
    int i = blockIdx.x * blockDim.x + threadIdx.x;
    if (i >= HDIM * CCTX / 2) return;
    int d = i / (CCTX / 2), cc = i % (CCTX / 2);
    float x0 = src[d * CCTX + 2 * cc], x1 = src[d * CCTX + 2 * cc + 1];
    float h0, l0, h1, l1;
    hilo(x0, h0, l0); hilo(x1, h1, l1);
    g_vhi[d * (SS / 2) + cc] = packbf2(h0, h1);
    g_vlo[d * (SS / 2) + cc] = packbf2(l0, l1);
}
// new V (from g_qkv) -> vhi/vlo cols CCTX/2.. + out_v
__global__ void packvnew_kernel(float* __restrict__ vout) {
    int i = blockIdx.x * blockDim.x + threadIdx.x;
    if (i >= HDIM * TT / 2) return;
    int d = i / (TT / 2), u = i % (TT / 2);
    float x0 = g_qkv[(long)(2 * u) * QKVW + 5 * HDIM + d];
    float x1 = g_qkv[(long)(2 * u + 1) * QKVW + 5 * HDIM + d];
    vout[d * TT + 2 * u] = x0;
    vout[d * TT + 2 * u + 1] = x1;
    float h0, l0, h1, l1;
    hilo(x0, h0, l0); hilo(x1, h1, l1);
    g_vhi[d * (SS / 2) + CCTX / 2 + u] = packbf2(h0, h1);
    g_vlo[d * (SS / 2) + CCTX / 2 + u] = packbf2(l0, l1);
}
__global__ void rmsnorm_kernel(const float* __restrict__ x, const float* __restrict__ w,
                               float* __restrict__ y) {
    int t = blockIdx.x;
    const float* xr = x + (long)t * DMODEL;
    float s = 0.f;
    for (int d = threadIdx.x; d < DMODEL; d += blockDim.x) { float v = xr[d]; s += v * v; }
    s = blockReduceSum(s);
    float rs = rsqrtf(s / DMODEL + 1e-6f);
    float* yr = y + (long)t * DMODEL;
    for (int d = threadIdx.x; d < DMODEL; d += blockDim.x)
        yr[d] = xr[d] * rs * (1.f + w[d]);
}
__global__ void addrms_kernel(const float* __restrict__ p, const float* __restrict__ w) {
    int t = blockIdx.x;
    const float* pr = p + (long)t * DMODEL;
    float s = 0.f;
    for (int d = threadIdx.x; d < DMODEL; d += blockDim.x) { float v = pr[d]; s += v * v; }
    s = blockReduceSum(s);
    float rs = rsqrtf(s / DMODEL + 1e-6f);
    float* hr = g_h + (long)t * DMODEL;
    for (int d = threadIdx.x; d < DMODEL; d += blockDim.x)
        hr[d] += pr[d] * rs * (1.f + w[d]);
}
// j<4: q head rms+rope -> g_q ; j==4: k rms+rope -> khi/klo row CCTX+t + out_k
__global__ void qkvpost_kernel(const float* __restrict__ qn_w, const float* __restrict__ kn_w,
                               const float* __restrict__ pcos, const float* __restrict__ psin,
                               float* __restrict__ kout) {
    int t = blockIdx.x, j = blockIdx.y, d = threadIdx.x;
    float v = g_qkv[(long)t * QKVW + j * HDIM + d];
    float s = blockReduceSum(v * v);
    float rs = rsqrtf(s / HDIM + 1e-6f);
    const float* wn = (j == 4) ? kn_w : qn_w;
    float n = v * rs * (1.f + wn[d]);
    __shared__ float sn[HDIM];
    sn[d] = n;
    __syncthreads();
    float rot = (d < HDIM / 2) ? -sn[d + HDIM / 2] : sn[d - HDIM / 2];
    float r = n * pcos[(long)t * HDIM + d] + rot * psin[(long)t * HDIM + d];
    if (j == 4) {
        kout[(long)t * HDIM + d] = r;
        float r1 = __shfl_down_sync(0xffffffffu, r, 1);
        if ((d & 1) == 0) {
            float h0, l0, h1, l1;
            hilo(r, h0, l0); hilo(r1, h1, l1);
            g_khi[(long)(CCTX + t) * (HDIM / 2) + d / 2] = packbf2(h0, h1);
            g_klo[(long)(CCTX + t) * (HDIM / 2) + d / 2] = packbf2(l0, l1);
        }
    } else {
        g_q[((long)j * TT + t) * HDIM + d] = r;
    }
}
__global__ void softmax_kernel(const float* __restrict__ mask) {
    int t = blockIdx.x, h = blockIdx.y;
    float* row = g_scores + ((long)h * TT + t) * SS;
    const float* mrow = mask + (long)t * SS;
    const float f = SCL / CAPV;
    float vloc[8];
    float mx = -3.4e38f;
    #pragma unroll
    for (int i = 0; i < 8; i++) {
        int s = threadIdx.x + i * 256;
        float val = tanhf(row[s] * f) * CAPV + mrow[s];
        vloc[i] = val;
        mx = fmaxf(mx, val);
    }
    mx = blockReduceMax(mx);
    float sum = 0.f;
    #pragma unroll
    for (int i = 0; i < 8; i++) { float e = expf(vloc[i] - mx); vloc[i] = e; sum += e; }
    sum = blockReduceSum(sum);
    float inv = 1.f / sum;
    #pragma unroll
    for (int i = 0; i < 8; i++) row[threadIdx.x + i * 256] = vloc[i] * inv;
}
__global__ void gelumul_kernel() {
    int i = blockIdx.x * blockDim.x + threadIdx.x;
    if (i < TT * FDIM) {
        float x = g_ffa[i], u = g_ffb[i];
        float g = 0.5f * x * (1.f + tanhf(0.7978845608028654f * (x + 0.044715f * x * x * x)));
        g_ffa[i] = g * u;
    }
}

// ---------- host ----------
static float* s_part;
static void runW(const float* A, int lda, const float* B, int ldb,
                 float* C, int ldc, int N, int K, int splits)
{
    dim3 grid(N / 128, splits, 1);
    mmagemm<1><<<grid, 256, SMEM_GEMM_BYTES>>>(A, lda, 0, B, nullptr, nullptr, ldb,
                                               C, ldc, 0, s_part, N, K, splits);
    if (splits > 1) {
        long total = (long)128 * N;
        reduce_kernel<<<(int)((total + 255) / 256), 256>>>(s_part, C, ldc, 0, N, splits, total);
    }
}
static void runP(const float* A, int lda, long sAb, const uint32_t* Bhi, const uint32_t* Blo,
                 float* C, int ldc, long sCb, int N, int K, int splits, int batches)
{
    dim3 grid(N / 128, splits, batches);
    mmagemm<2><<<grid, 256, SMEM_GEMM_BYTES>>>(A, lda, sAb, nullptr, Bhi, Blo, 0,
                                               C, ldc, sCb, s_part, N, K, splits);
    if (splits > 1) {
        long total = (long)batches * 128 * N;
        reduce_kernel<<<(int)((total + 255) / 256), 256>>>(s_part, C, ldc, sCb, N, splits, total);
    }
}

extern "C" void kernel_launch(void* const* d_in, const int* in_sizes, int n_in,
                              void* d_out, int out_size)
{
    const float* embeddings  = (const float*)d_in[0];
    const float* mask_global = (const float*)d_in[1];
    const float* mask_local  = (const float*)d_in[2];
    const float* pe_cos      = (const float*)d_in[3];
    const float* pe_sin      = (const float*)d_in[4];
    const float* pe_cos_loc  = (const float*)d_in[5];
    const float* pe_sin_loc  = (const float*)d_in[6];
    const float* kv_k        = (const float*)d_in[7];
    const float* kv_v        = (const float*)d_in[8];
    const float* pre_attn_w  = (const float*)d_in[9];
    const float* q_norm_w    = (const float*)d_in[10];
    const float* k_norm_w    = (const float*)d_in[11];
    const float* post_attn_w = (const float*)d_in[12];
    const float* pre_ff_w    = (const float*)d_in[13];
    const float* post_ff_w   = (const float*)d_in[14];
    const float* final_w     = (const float*)d_in[15];
    const float* w_qkv       = (const float*)d_in[16];
    const float* w_out       = (const float*)d_in[17];
    const float* w_gate      = (const float*)d_in[18];
    const float* w_up        = (const float*)d_in[19];
    const float* w_down      = (const float*)d_in[20];
    const float* w_lm        = (const float*)d_in[21];

    float* out = (float*)d_out;
    float* out_logits = out;
    float* out_k = out + (long)TT * VOC;
    float* out_v = out_k + (long)NL * TT * HDIM;

    float *ph, *px, *pqkv, *pq, *psc, *pao, *ppr, *pfa, *pfb;
    uint32_t *pkh, *pkl, *pvh, *pvl;
    cudaGetSymbolAddress((void**)&ph, g_h);
    cudaGetSymbolAddress((void**)&px, g_x);
    cudaGetSymbolAddress((void**)&pqkv, g_qkv);
    cudaGetSymbolAddress((void**)&pq, g_q);
    cudaGetSymbolAddress((void**)&pkh, g_khi);
    cudaGetSymbolAddress((void**)&pkl, g_klo);
    cudaGetSymbolAddress((void**)&pvh, g_vhi);
    cudaGetSymbolAddress((void**)&pvl, g_vlo);
    cudaGetSymbolAddress((void**)&psc, g_scores);
    cudaGetSymbolAddress((void**)&pao, g_attno);
    cudaGetSymbolAddress((void**)&ppr, g_proj);
    cudaGetSymbolAddress((void**)&pfa, g_ffa);
    cudaGetSymbolAddress((void**)&pfb, g_ffb);
    cudaGetSymbolAddress((void**)&s_part, g_part);

    copy_kernel<<<(TT * DMODEL + 255) / 256, 256>>>(embeddings, ph, TT * DMODEL);

    for (int i = 0; i < NL; i++) {
        bool is_local = ((i + 1) % 6) == 0;
        const float* pcos = is_local ? pe_cos_loc : pe_cos;
        const float* psin = is_local ? pe_sin_loc : pe_sin;
        const float* mask = is_local ? mask_local : mask_global;

        rmsnorm_kernel<<<TT, 256>>>(ph, pre_attn_w + (long)i * DMODEL, px);

        // qkv: 128x1152x1536, splits 18 (Kc=64) -> 216 CTAs
        runW(px, DMODEL, w_qkv + (long)i * DMODEL * QKVW, QKVW, pqkv, QKVW, QKVW, DMODEL, 18);

        packk_kernel<<<(CCTX * HDIM / 2 + 255) / 256, 256>>>(kv_k + (long)i * CCTX * HDIM);
        packv_kernel<<<(HDIM * CCTX / 2 + 255) / 256, 256>>>(kv_v + (long)i * HDIM * CCTX);
        packvnew_kernel<<<(HDIM * TT / 2 + 255) / 256, 256>>>(out_v + (long)i * HDIM * TT);

        qkvpost_kernel<<<dim3(TT, 5), HDIM>>>(q_norm_w + (long)i * HDIM,
                                              k_norm_w + (long)i * HDIM, pcos, psin,
                                              out_k + (long)i * TT * HDIM);

        // scores: per-head 128x2048x256, packed K, splits 4 -> 256 CTAs
        runP(pq, HDIM, (long)TT * HDIM, pkh, pkl,
             psc, SS, (long)TT * SS, SS, HDIM, 4, NHD);

        softmax_kernel<<<dim3(TT, NHD), 256>>>(mask);

        // attn@V: per-head 128x256x2048, packed V, splits 32 -> 256 CTAs
        runP(psc, SS, (long)TT * SS, pvh, pvl,
             pao, NHD * HDIM, (long)HDIM, HDIM, SS, 32, NHD);

        // proj: 128x1152x1024, splits 16 (Kc=64) -> 144 CTAs
        runW(pao, NHD * HDIM, w_out + (long)i * NHD * HDIM * DMODEL, DMODEL,
             ppr, DMODEL, DMODEL, NHD * HDIM, 16);

        addrms_kernel<<<TT, 256>>>(ppr, post_attn_w + (long)i * DMODEL);
        rmsnorm_kernel<<<TT, 256>>>(ph, pre_ff_w + (long)i * DMODEL, px);

        // gate/up: 128x6912x1152, splits 4 (Kc=288) -> 216 CTAs each
        runW(px, DMODEL, w_gate + (long)i * DMODEL * FDIM, FDIM, pfa, FDIM, FDIM, DMODEL, 4);
        runW(px, DMODEL, w_up + (long)i * DMODEL * FDIM, FDIM, pfb, FDIM, FDIM, DMODEL, 4);

        gelumul_kernel<<<(TT * FDIM + 255) / 256, 256>>>();

        // down: 128x1152x6912, splits 24 (Kc=288) -> 216 CTAs
        runW(pfa, FDIM, w_down + (long)i * FDIM * DMODEL, DMODEL, ppr, DMODEL, DMODEL, FDIM, 24);

        addrms_kernel<<<TT, 256>>>(ppr, post_ff_w + (long)i * DMODEL);
    }

    rmsnorm_kernel<<<TT, 256>>>(ph, final_w, px);
    // lm: 128x32768x1152, splits 2 (Kc=576) -> 512 CTAs
    runW(px, DMODEL, w_lm, VOC, out_logits, VOC, VOC, DMODEL, 2);
}

// round 13
// speedup vs baseline: 1.0053x; 1.0053x over previous
#include <cuda_runtime.h>
#include <cuda_bf16.h>
#include <math.h>
#include <stdint.h>

#define NL 12
#define DMODEL 1152
#define NHD 4
#define HDIM 256
#define FDIM 6912
#define VOC 32768
#define TT 128
#define CCTX 1920
#define SS 2048
#define QKVW 1536
#define CAPV 50.0f
#define SCL 0.0625f

__device__ __align__(256) float g_h[TT * DMODEL];
__device__ __align__(256) float g_x[TT * DMODEL];
__device__ __align__(256) float g_qkv[TT * QKVW];
__device__ __align__(256) float g_q[NHD * TT * HDIM];
__device__ __align__(256) uint32_t g_khi[SS * HDIM / 2];
__device__ __align__(256) uint32_t g_klo[SS * HDIM / 2];
__device__ __align__(256) uint32_t g_vhi[HDIM * SS / 2];
__device__ __align__(256) uint32_t g_vlo[HDIM * SS / 2];
__device__ __align__(256) float g_scores[NHD * TT * SS];
__device__ __align__(256) float g_attno[TT * NHD * HDIM];
__device__ __align__(256) float g_proj[TT * DMODEL];
__device__ __align__(256) float g_ff[2 * TT * FDIM];
__device__ __align__(256) float g_part[8 * 1024 * 1024];

// ---------- helpers ----------
__device__ __forceinline__ uint32_t smem_u32(const void* p) {
    uint32_t a;
    asm("{ .reg .u64 t; cvta.to.shared.u64 t, %1; cvt.u32.u64 %0, t; }" : "=r"(a) : "l"(p));
    return a;
}
__device__ __forceinline__ uint32_t sw128(uint32_t o) { return o ^ ((o >> 3) & 0x70u); }
__device__ __forceinline__ uint32_t packbf2(float a, float b) {
    __nv_bfloat162 t = __floats2bfloat162_rn(a, b);
    return *(uint32_t*)&t;
}
__device__ __forceinline__ void hilo(float v, float& h, float& l) {
    __nv_bfloat16 hb = __float2bfloat16_rn(v);
    h = __bfloat162float(hb);
    l = v - h;
}
__device__ __forceinline__ void ldm4(uint32_t* r, uint32_t a) {
    asm volatile("ldmatrix.sync.aligned.m8n8.x4.shared.b16 {%0,%1,%2,%3}, [%4];"
                 : "=r"(r[0]), "=r"(r[1]), "=r"(r[2]), "=r"(r[3]) : "r"(a));
}
__device__ __forceinline__ void mma16816(float* c, const uint32_t* a, uint32_t b0, uint32_t b1) {
    asm volatile(
        "mma.sync.aligned.m16n8k16.row.col.f32.bf16.bf16.f32 "
        "{%0,%1,%2,%3}, {%4,%5,%6,%7}, {%8,%9}, {%0,%1,%2,%3};"
        : "+f"(c[0]), "+f"(c[1]), "+f"(c[2]), "+f"(c[3])
        : "r"(a[0]), "r"(a[1]), "r"(a[2]), "r"(a[3]), "r"(b0), "r"(b1));
}
__device__ __forceinline__ void st8(uint32_t a, uint32_t v0, uint32_t v1) {
    asm volatile("st.shared.v2.b32 [%0], {%1,%2};" :: "r"(a), "r"(v0), "r"(v1) : "memory");
}
__device__ __forceinline__ void store4(uint32_t base, uint32_t ob, float4 v) {
    float h0, l0, h1, l1, h2, l2, h3, l3;
    hilo(v.x, h0, l0); hilo(v.y, h1, l1); hilo(v.z, h2, l2); hilo(v.w, h3, l3);
    st8(base + sw128(ob),      packbf2(h0, h1), packbf2(h2, h3));
    st8(base + sw128(ob + 64), packbf2(l0, l1), packbf2(l2, l3));
}
__device__ __forceinline__ void cpa16(uint32_t dst, const void* src) {
    asm volatile("cp.async.cg.shared.global [%0], [%1], 16;" :: "r"(dst), "l"(src) : "memory");
}
__device__ __forceinline__ void cpa_commit() {
    asm volatile("cp.async.commit_group;" ::: "memory");
}
__device__ __forceinline__ void cpa_wait0() {
    asm volatile("cp.async.wait_group 0;" ::: "memory");
}

// ============================================================
// bf16x3 mma GEMM. Double-buffered 64KB smem, 2 CTAs/SM.
// BMODE 1: B fp32 [K,N] (N contig); dual-B via Bf1 when batch==1.
// BMODE 2: B pre-packed bf16 hi/lo u32 [N][K/2]; cp.async fill.
// ============================================================
#define SMEM_GEMM_BYTES 65536

template <int BMODE>
__global__ void __launch_bounds__(256, 2) mmagemm(
    const float* __restrict__ Aall, int lda, long sAb,
    const float* __restrict__ Bf, const float* __restrict__ Bf1,
    const uint32_t* __restrict__ Bhi, const uint32_t* __restrict__ Blo,
    int ldb, float* __restrict__ Call, int ldc, long sCb,
    float* __restrict__ Cpart, int N, int K, int splits)
{
    extern __shared__ char smraw[];
    const uint32_t sb = smem_u32(smraw);
    const int tid = threadIdx.x;
    const int lane = tid & 31, w = tid >> 5;
    const int wm = w & 1, wn = w >> 1;
    const int nb = blockIdx.x, split = blockIdx.y, batch = blockIdx.z;
    const int Kc = K / splits;
    const int NC = Kc >> 5;

    const float* A = Aall + (long)batch * sAb + (long)split * Kc;
    const float* Bsel = (BMODE == 1 && Bf1 && batch == 1) ? Bf1 : Bf;
    const float* BfT = (BMODE == 1) ? (Bsel + (long)((long)split * Kc) * ldb + nb * 128) : nullptr;
    const int Kh = K >> 1;
    const long bpk = (long)(nb * 128) * Kh + (split * Kc >> 1);

    float c[4][4][4];
    #pragma unroll
    for (int a = 0; a < 4; a++)
        #pragma unroll
        for (int b = 0; b < 4; b++)
            #pragma unroll
            for (int r = 0; r < 4; r++) c[a][b][r] = 0.f;

    const int row = tid >> 1, half = tid & 1;
    const int bn = tid & 127, bkg = tid >> 7;

    float4 ra[4];
    float rbs[16];

    auto loadA = [&](int i) {
        const float* ap = A + (long)row * lda + i * 32 + half * 16;
        #pragma unroll
        for (int q = 0; q < 4; q++) ra[q] = ((const float4*)ap)[q];
    };
    auto loadB1 = [&](int i) {
        const float* bp = BfT + ((long)i * 32 + bkg * 16) * ldb + bn;
        #pragma unroll
        for (int q = 0; q < 16; q++) rbs[q] = bp[(long)q * ldb];
    };
    auto storeA = [&](int p) {
        const uint32_t base = sb + p * 16384;
        const uint32_t o = row * 128 + half * 32;
        #pragma unroll
        for (int q = 0; q < 4; q++) store4(base, o + q * 8, ra[q]);
    };
    auto storeB1 = [&](int p) {
        const uint32_t base = sb + 32768 + p * 16384;
        const uint32_t o = bn * 128 + bkg * 32;
        #pragma unroll
        for (int g = 0; g < 4; g++) {
            float4 v = make_float4(rbs[g * 4], rbs[g * 4 + 1], rbs[g * 4 + 2], rbs[g * 4 + 3]);
            store4(base, o + g * 8, v);
        }
    };
    auto cpB2 = [&](int i, int p) {
        const uint32_t base = sb + 32768 + p * 16384;
        const long u = bpk + (long)row * Kh + i * 16 + half * 8;
        const uint32_t o = row * 128 + half * 32;
        cpa16(base + sw128(o),      Bhi + u);
        cpa16(base + sw128(o + 16), Bhi + u + 4);
        cpa16(base + sw128(o + 64), Blo + u);
        cpa16(base + sw128(o + 80), Blo + u + 4);
        cpa_commit();
    };

    const int m0 = wm * 64, n0 = wn * 32;
    const uint32_t lrow = lane & 15;
    const uint32_t lsel = (lane >> 4) * 16;

    auto mmachunk = [&](int p) {
        const uint32_t ab = sb + p * 16384;
        const uint32_t bb = sb + 32768 + p * 16384;
        #pragma unroll
        for (int j = 0; j < 2; j++) {
            const uint32_t cb = j * 32;
            uint32_t ahi[4][4], alo[4][4], bhi[2][4], blo[2][4];
            #pragma unroll
            for (int mt = 0; mt < 4; mt++) {
                uint32_t o = (m0 + mt * 16 + lrow) * 128 + cb + lsel;
                ldm4(ahi[mt], ab + sw128(o));
                ldm4(alo[mt], ab + sw128(o + 64));
            }
            #pragma unroll
            for (int pp = 0; pp < 2; pp++) {
                uint32_t o = (n0 + pp * 16 + lrow) * 128 + cb + lsel;
                ldm4(bhi[pp], bb + sw128(o));
                ldm4(blo[pp], bb + sw128(o + 64));
            }
            #pragma unroll
            for (int mt = 0; mt < 4; mt++)
                #pragma unroll
                for (int nt = 0; nt < 4; nt++) {
                    int pp = nt >> 1, qq = nt & 1;
                    mma16816(c[mt][nt], ahi[mt], bhi[pp][qq], bhi[pp][qq + 2]);
                    mma16816(c[mt][nt], alo[mt], bhi[pp][qq], bhi[pp][qq + 2]);
                    mma16816(c[mt][nt], ahi[mt], blo[pp][qq], blo[pp][qq + 2]);
                }
        }
    };

    // ---- pipeline ----
    loadA(0);
    if (BMODE == 2) cpB2(0, 0);
    else loadB1(0);
    storeA(0);
    if (BMODE == 1) storeB1(0);
    else cpa_wait0();
    __syncthreads();
    for (int i = 0; i < NC; i++) {
        const int p = i & 1;
        if (i + 1 < NC) {
            if (BMODE == 2) cpB2(i + 1, p ^ 1);
            loadA(i + 1);
            if (BMODE == 1) loadB1(i + 1);
        }
        mmachunk(p);
        __syncthreads();
        if (i + 1 < NC) {
            storeA(p ^ 1);
            if (BMODE == 1) storeB1(p ^ 1);
            else cpa_wait0();
            __syncthreads();
        }
    }

    // ---- epilogue ----
    float* Cb;
    long ldx;
    if (splits == 1) { Cb = Call + (long)batch * sCb + nb * 128; ldx = ldc; }
    else { Cb = Cpart + ((long)(batch * splits + split) * 128) * N + nb * 128; ldx = N; }
    #pragma unroll
    for (int mt = 0; mt < 4; mt++)
        #pragma unroll
        for (int nt = 0; nt < 4; nt++) {
            int r0 = m0 + mt * 16 + (lane >> 2);
            int c0 = n0 + nt * 8 + (lane & 3) * 2;
            *(float2*)&Cb[(long)r0 * ldx + c0] = make_float2(c[mt][nt][0], c[mt][nt][1]);
            *(float2*)&Cb[(long)(r0 + 8) * ldx + c0] = make_float2(c[mt][nt][2], c[mt][nt][3]);
        }
}

__global__ void reduce_kernel(const float* __restrict__ part, float* __restrict__ C,
                              int ldc, long sCb, int N, int splits, long total)
{
    long idx = (long)blockIdx.x * blockDim.x + threadIdx.x;
    if (idx >= total) return;
    int n = (int)(idx % N);
    long r = idx / N;
    int m = (int)(r % 128);
    int b = (int)(r / 128);
    float s = 0.f;
    for (int sp = 0; sp < splits; sp++)
        s += part[((long)(b * splits + sp) * 128 + m) * N + n];
    C[(long)b * sCb + (long)m * ldc + n] = s;
}

// ---------- reductions ----------
__device__ __forceinline__ float blockReduceSum(float v) {
    __shared__ float sh[33];
    __syncthreads();
    int lane = threadIdx.x & 31, wid = threadIdx.x >> 5;
    #pragma unroll
    for (int o = 16; o; o >>= 1) v += __shfl_xor_sync(0xffffffffu, v, o);
    if (lane == 0) sh[wid] = v;
    __syncthreads();
    int nw = (blockDim.x + 31) >> 5;
    v = (threadIdx.x < nw) ? sh[threadIdx.x] : 0.f;
    if (wid == 0) {
        #pragma unroll
        for (int o = 16; o; o >>= 1) v += __shfl_xor_sync(0xffffffffu, v, o);
        if (lane == 0) sh[32] = v;
    }
    __syncthreads();
    return sh[32];
}
__device__ __forceinline__ float blockReduceMax(float v) {
    __shared__ float sh[33];
    __syncthreads();
    int lane = threadIdx.x & 31, wid = threadIdx.x >> 5;
    #pragma unroll
    for (int o = 16; o; o >>= 1) v = fmaxf(v, __shfl_xor_sync(0xffffffffu, v, o));
    if (lane == 0) sh[wid] = v;
    __syncthreads();
    int nw = (blockDim.x + 31) >> 5;
    v = (threadIdx.x < nw) ? sh[threadIdx.x] : -3.4e38f;
    if (wid == 0) {
        #pragma unroll
        for (int o = 16; o; o >>= 1) v = fmaxf(v, __shfl_xor_sync(0xffffffffu, v, o));
        if (lane == 0) sh[32] = v;
    }
    __syncthreads();
    return sh[32];
}

// ---------- elementwise / pack / norm ----------
__global__ void copy_kernel(const float* __restrict__ s, float* __restrict__ d, int n) {
    int i = blockIdx.x * blockDim.x + threadIdx.x;
    if (i < n) d[i] = s[i];
}
// y=0: pack K cache; y=1: pack V cache
__global__ void packkv_kernel(const float* __restrict__ ksrc, const float* __restrict__ vsrc) {
    int i = blockIdx.x * blockDim.x + threadIdx.x;
    if (blockIdx.y == 0) {
        if (i >= CCTX * HDIM / 2) return;
        int r = i / (HDIM / 2), cc = i % (HDIM / 2);
        float x0 = ksrc[r * HDIM + 2 * cc], x1 = ksrc[r * HDIM + 2 * cc + 1];
        float h0, l0, h1, l1;
        hilo(x0, h0, l0); hilo(x1, h1, l1);
        g_khi[r * (HDIM / 2) + cc] = packbf2(h0, h1);
        g_klo[r * (HDIM / 2) + cc] = packbf2(l0, l1);
    } else {
        if (i >= HDIM * CCTX / 2) return;
        int d = i / (CCTX / 2), cc = i % (CCTX / 2);
        float x0 = vsrc[d * CCTX + 2 * cc], x1 = vsrc[d * CCTX + 2 * cc + 1];
        float h0, l0, h1, l1;
        hilo(x0, h0, l0); hilo(x1, h1, l1);
        g_vhi[d * (SS / 2) + cc] = packbf2(h0, h1);
        g_vlo[d * (SS / 2) + cc] = packbf2(l0, l1);
    }
}
__global__ void rmsnorm_kernel(const float* __restrict__ x, const float* __restrict__ w,
                               float* __restrict__ y) {
    int t = blockIdx.x;
    const float* xr = x + (long)t * DMODEL;
    float s = 0.f;
    for (int d = threadIdx.x; d < DMODEL; d += blockDim.x) { float v = xr[d]; s += v * v; }
    s = blockReduceSum(s);
    float rs = rsqrtf(s / DMODEL + 1e-6f);
    float* yr = y + (long)t * DMODEL;
    for (int d = threadIdx.x; d < DMODEL; d += blockDim.x)
        yr[d] = xr[d] * rs * (1.f + w[d]);
}
// h += rms(p, wa); y = rms(h, wn)
__global__ void addnorm_kernel(const float* __restrict__ p, const float* __restrict__ wa,
                               const float* __restrict__ wn, float* __restrict__ y) {
    int t = blockIdx.x;
    const float* pr = p + (long)t * DMODEL;
    float* hr = g_h + (long)t * DMODEL;
    float s = 0.f;
    for (int d = threadIdx.x; d < DMODEL; d += blockDim.x) { float v = pr[d]; s += v * v; }
    s = blockReduceSum(s);
    float rs = rsqrtf(s / DMODEL + 1e-6f);
    float s2 = 0.f;
    for (int d = threadIdx.x; d < DMODEL; d += blockDim.x) {
        float nh = hr[d] + pr[d] * rs * (1.f + wa[d]);
        hr[d] = nh;
        s2 += nh * nh;
    }
    s2 = blockReduceSum(s2);
    float rs2 = rsqrtf(s2 / DMODEL + 1e-6f);
    float* yr = y + (long)t * DMODEL;
    for (int d = threadIdx.x; d < DMODEL; d += blockDim.x)
        yr[d] = hr[d] * rs2 * (1.f + wn[d]);
}
// j<4: q rms+rope -> g_q ; j=4: k rms+rope -> pack + out_k ; j=5: v -> pack + out_v
__global__ void qkvpost_kernel(const float* __restrict__ qn_w, const float* __restrict__ kn_w,
                               const float* __restrict__ pcos, const float* __restrict__ psin,
                               float* __restrict__ kout, float* __restrict__ vout) {
    int t = blockIdx.x, j = blockIdx.y, d = threadIdx.x;
    float v = g_qkv[(long)t * QKVW + j * HDIM + d];
    if (j == 5) {
        vout[(long)d * TT + t] = v;
        if ((t & 1) == 0) {
            float x1 = g_qkv[(long)(t + 1) * QKVW + 5 * HDIM + d];
            float h0, l0, h1, l1;
            hilo(v, h0, l0); hilo(x1, h1, l1);
            g_vhi[(long)d * (SS / 2) + CCTX / 2 + t / 2] = packbf2(h0, h1);
            g_vlo[(long)d * (SS / 2) + CCTX / 2 + t / 2] = packbf2(l0, l1);
        }
        return;
    }
    float s = blockReduceSum(v * v);
    float rs = rsqrtf(s / HDIM + 1e-6f);
    const float* wn = (j == 4) ? kn_w : qn_w;
    float n = v * rs * (1.f + wn[d]);
    __shared__ float sn[HDIM];
    sn[d] = n;
    __syncthreads();
    float rot = (d < HDIM / 2) ? -sn[d + HDIM / 2] : sn[d - HDIM / 2];
    float r = n * pcos[(long)t * HDIM + d] + rot * psin[(long)t * HDIM + d];
    if (j == 4) {
        kout[(long)t * HDIM + d] = r;
        float r1 = __shfl_down_sync(0xffffffffu, r, 1);
        if ((d & 1) == 0) {
            float h0, l0, h1, l1;
            hilo(r, h0, l0); hilo(r1, h1, l1);
            g_khi[(long)(CCTX + t) * (HDIM / 2) + d / 2] = packbf2(h0, h1);
            g_klo[(long)(CCTX + t) * (HDIM / 2) + d / 2] = packbf2(l0, l1);
        }
    } else {
        g_q[((long)j * TT + t) * HDIM + d] = r;
    }
}
__global__ void softmax_kernel(const float* __restrict__ mask) {
    int t = blockIdx.x, h = blockIdx.y;
    float* row = g_scores + ((long)h * TT + t) * SS;
    const float* mrow = mask + (long)t * SS;
    const float f = SCL / CAPV;
    float vloc[8];
    float mx = -3.4e38f;
    #pragma unroll
    for (int i = 0; i < 8; i++) {
        int s = threadIdx.x + i * 256;
        float val = tanhf(row[s] * f) * CAPV + mrow[s];
        vloc[i] = val;
        mx = fmaxf(mx, val);
    }
    mx = blockReduceMax(mx);
    float sum = 0.f;
    #pragma unroll
    for (int i = 0; i < 8; i++) { float e = expf(vloc[i] - mx); vloc[i] = e; sum += e; }
    sum = blockReduceSum(sum);
    float inv = 1.f / sum;
    #pragma unroll
    for (int i = 0; i < 8; i++) row[threadIdx.x + i * 256] = vloc[i] * inv;
}
__global__ void gelumul_kernel() {
    int i = blockIdx.x * blockDim.x + threadIdx.x;
    if (i < TT * FDIM) {
        float x = g_ff[i], u = g_ff[TT * FDIM + i];
        float g = 0.5f * x * (1.f + tanhf(0.7978845608028654f * (x + 0.044715f * x * x * x)));
        g_ff[i] = g * u;
    }
}

// ---------- host ----------
static float* s_part;
static void runW(const float* A, int lda, const float* B, const float* B1, int ldb,
                 float* C, int ldc, long sCb, int N, int K, int splits, int nb)
{
    dim3 grid(N / 128, splits, nb);
    mmagemm<1><<<grid, 256, SMEM_GEMM_BYTES>>>(A, lda, 0, B, B1, nullptr, nullptr, ldb,
                                               C, ldc, sCb, s_part, N, K, splits);
    if (splits > 1) {
        long total = (long)nb * 128 * N;
        reduce_kernel<<<(int)((total + 255) / 256), 256>>>(s_part, C, ldc, sCb, N, splits, total);
    }
}
static void runP(const float* A, int lda, long sAb, const uint32_t* Bhi, const uint32_t* Blo,
                 float* C, int ldc, long sCb, int N, int K, int splits, int batches)
{
    dim3 grid(N / 128, splits, batches);
    mmagemm<2><<<grid, 256, SMEM_GEMM_BYTES>>>(A, lda, sAb, nullptr, nullptr, Bhi, Blo, 0,
                                               C, ldc, sCb, s_part, N, K, splits);
    if (splits > 1) {
        long total = (long)batches * 128 * N;
        reduce_kernel<<<(int)((total + 255) / 256), 256>>>(s_part, C, ldc, sCb, N, splits, total);
    }
}

extern "C" void kernel_launch(void* const* d_in, const int* in_sizes, int n_in,
                              void* d_out, int out_size)
{
    const float* embeddings  = (const float*)d_in[0];
    const float* mask_global = (const float*)d_in[1];
    const float* mask_local  = (const float*)d_in[2];
    const float* pe_cos      = (const float*)d_in[3];
    const float* pe_sin      = (const float*)d_in[4];
    const float* pe_cos_loc  = (const float*)d_in[5];
    const float* pe_sin_loc  = (const float*)d_in[6];
    const float* kv_k        = (const float*)d_in[7];
    const float* kv_v        = (const float*)d_in[8];
    const float* pre_attn_w  = (const float*)d_in[9];
    const float* q_norm_w    = (const float*)d_in[10];
    const float* k_norm_w    = (const float*)d_in[11];
    const float* post_attn_w = (const float*)d_in[12];
    const float* pre_ff_w    = (const float*)d_in[13];
    const float* post_ff_w   = (const float*)d_in[14];
    const float* final_w     = (const float*)d_in[15];
    const float* w_qkv       = (const float*)d_in[16];
    const float* w_out       = (const float*)d_in[17];
    const float* w_gate      = (const float*)d_in[18];
    const float* w_up        = (const float*)d_in[19];
    const float* w_down      = (const float*)d_in[20];
    const float* w_lm        = (const float*)d_in[21];

    cudaFuncSetAttribute(mmagemm<1>, cudaFuncAttributeMaxDynamicSharedMemorySize, SMEM_GEMM_BYTES);
    cudaFuncSetAttribute(mmagemm<2>, cudaFuncAttributeMaxDynamicSharedMemorySize, SMEM_GEMM_BYTES);

    float* out = (float*)d_out;
    float* out_logits = out;
    float* out_k = out + (long)TT * VOC;
    float* out_v = out_k + (long)NL * TT * HDIM;

    float *ph, *px, *pqkv, *pq, *psc, *pao, *ppr, *pff;
    uint32_t *pkh, *pkl, *pvh, *pvl;
    cudaGetSymbolAddress((void**)&ph, g_h);
    cudaGetSymbolAddress((void**)&px, g_x);
    cudaGetSymbolAddress((void**)&pqkv, g_qkv);
    cudaGetSymbolAddress((void**)&pq, g_q);
    cudaGetSymbolAddress((void**)&pkh, g_khi);
    cudaGetSymbolAddress((void**)&pkl, g_klo);
    cudaGetSymbolAddress((void**)&pvh, g_vhi);
    cudaGetSymbolAddress((void**)&pvl, g_vlo);
    cudaGetSymbolAddress((void**)&psc, g_scores);
    cudaGetSymbolAddress((void**)&pao, g_attno);
    cudaGetSymbolAddress((void**)&ppr, g_proj);
    cudaGetSymbolAddress((void**)&pff, g_ff);
    cudaGetSymbolAddress((void**)&s_part, g_part);

    copy_kernel<<<(TT * DMODEL + 255) / 256, 256>>>(embeddings, ph, TT * DMODEL);
    rmsnorm_kernel<<<TT, 256>>>(ph, pre_attn_w, px);

    for (int i = 0; i < NL; i++) {
        bool is_local = ((i + 1) % 6) == 0;
        const float* pcos = is_local ? pe_cos_loc : pe_cos;
        const float* psin = is_local ? pe_sin_loc : pe_sin;
        const float* mask = is_local ? mask_local : mask_global;

        // qkv: 128x1536x1152, splits 12 (Kc=96) -> 144 CTAs
        runW(px, DMODEL, w_qkv + (long)i * DMODEL * QKVW, nullptr, QKVW,
             pqkv, QKVW, 0, QKVW, DMODEL, 12, 1);

        packkv_kernel<<<dim3((CCTX * HDIM / 2 + 255) / 256, 2), 256>>>(
            kv_k + (long)i * CCTX * HDIM, kv_v + (long)i * HDIM * CCTX);

        qkvpost_kernel<<<dim3(TT, 6), HDIM>>>(q_norm_w + (long)i * HDIM,
                                              k_norm_w + (long)i * HDIM, pcos, psin,
                                              out_k + (long)i * TT * HDIM,
                                              out_v + (long)i * HDIM * TT);

        // scores: per-head 128x2048 (K=256), packed K, splits 2 -> 128 CTAs
        runP(pq, HDIM, (long)TT * HDIM, pkh, pkl,
             psc, SS, (long)TT * SS, SS, HDIM, 2, NHD);

        softmax_kernel<<<dim3(TT, NHD), 256>>>(mask);

        // attn@V: per-head 128x256 (K=2048), packed V, splits 16 -> 128 CTAs
        runP(psc, SS, (long)TT * SS, pvh, pvl,
             pao, NHD * HDIM, (long)HDIM, HDIM, SS, 16, NHD);

        // proj: 128x1152 (K=1024), splits 16 (Kc=64) -> 144 CTAs
        runW(pao, NHD * HDIM, w_out + (long)i * NHD * HDIM * DMODEL, nullptr, DMODEL,
             ppr, DMODEL, 0, DMODEL, NHD * HDIM, 16, 1);

        addnorm_kernel<<<TT, 256>>>(ppr, post_attn_w + (long)i * DMODEL,
                                    pre_ff_w + (long)i * DMODEL, px);

        // gate+up fused: 128x6912 (K=1152), splits 3 (Kc=384), z=2 -> 324 CTAs
        runW(px, DMODEL, w_gate + (long)i * DMODEL * FDIM,
             w_up + (long)i * DMODEL * FDIM, FDIM,
             pff, FDIM, (long)TT * FDIM, FDIM, DMODEL, 3, 2);

        gelumul_kernel<<<(TT * FDIM + 255) / 256, 256>>>();

        // down: 128x1152 (K=6912), splits 18 (Kc=384) -> 162 CTAs
        runW(pff, FDIM, w_down + (long)i * FDIM * DMODEL, nullptr, DMODEL,
             ppr, DMODEL, 0, DMODEL, FDIM, 18, 1);

        const float* wnext = (i + 1 < NL) ? (pre_attn_w + (long)(i + 1) * DMODEL) : final_w;
        addnorm_kernel<<<TT, 256>>>(ppr, post_ff_w + (long)i * DMODEL, wnext, px);
    }

    // lm: 128x32768 (K=1152), splits 1 -> 256 CTAs
    runW(px, DMODEL, w_lm, nullptr, VOC, out_logits, VOC, 0, VOC, DMODEL, 1, 1);
}